// round 5
// baseline (speedup 1.0000x reference)
#include <cuda_runtime.h>
#include <cuda_bf16.h>
#include <cstdint>

// ---------------- problem constants ----------------
#define N_TOT 8192
#define D     128
#define IPC_C 512
#define ROW0  7680            // bz - IPC
#define NCOL  7680            // unmasked columns [0, 7680)
#define BM    128
#define BN    256
#define NTIL  (NCOL / BN)     // 30 column tiles
#define ETIL  (1024 / BN)     // tiles [0,4) are the easy region (exact boundary)
#define NBLK  (NTIL * (IPC_C / BM))   // 120 blocks = one wave
#define LDA   132             // padded smem stride (floats); 132*4 % 16 == 0

// ---------------- device globals (no allocs allowed) ----------------
__device__ float g_fn[N_TOT * D];        // normalized, tf32-rounded
__device__ float g_part[NTIL * IPC_C];   // [colTile][row] partial maxima
__device__ int   g_done;                 // zero-init; reset to 0 each replay

#define CP_ASYNC16(dst_u32, src_ptr) \
    asm volatile("cp.async.cg.shared.global [%0], [%1], 16;" \
                 :: "r"(dst_u32), "l"(src_ptr) : "memory")
#define CP_COMMIT()  asm volatile("cp.async.commit_group;" ::: "memory")
#define CP_WAIT(n)   asm volatile("cp.async.wait_group %0;" :: "n"(n) : "memory")

// ---------------- kernel 1: normalize + tf32 round ----------------
__global__ void __launch_bounds__(256) prep_kernel(const float* __restrict__ f) {
    int row  = blockIdx.x * 8 + (threadIdx.x >> 5);
    int lane = threadIdx.x & 31;
    float4 v = ((const float4*)(f + (size_t)row * D))[lane];
    float s = v.x * v.x + v.y * v.y + v.z * v.z + v.w * v.w;
    #pragma unroll
    for (int o = 16; o; o >>= 1) s += __shfl_xor_sync(0xffffffffu, s, o);
    float inv = rsqrtf(s);
    if (!(s > 1e-24f)) inv = 1e12f;

    float x[4] = {v.x * inv, v.y * inv, v.z * inv, v.w * inv};
    uint32_t t[4];
    #pragma unroll
    for (int j = 0; j < 4; j++)
        asm("cvt.rna.tf32.f32 %0, %1;" : "=r"(t[j]) : "f"(x[j]));
    *(uint4*)(g_fn + (size_t)row * D + lane * 4) = *(uint4*)t;
}

// ---------------- kernel 2: tf32 mma GEMM + row-max + fused finalize ----------------
// 1024 threads = 32 warps in a 4(m) x 8(n) grid; warp tile 32x32 (mt=2, nt=4).
// smem: As[128][132], Bs[256][132]  (198 KB dynamic)
#define SMEM_FLOATS (BM * LDA + BN * LDA)

__global__ void __launch_bounds__(1024, 1) gemm_kernel(const float* __restrict__ a_scl,
                                                       float* __restrict__ out) {
    extern __shared__ float sm[];
    float* As = sm;                 // [128][132]
    float* Bs = sm + BM * LDA;      // [256][132]

    const int tid  = threadIdx.x;
    const int lane = tid & 31;
    const int w    = tid >> 5;
    const int wm   = w >> 3;        // 0..3 -> 32-row strip
    const int wn   = w & 7;         // 0..7 -> 32-col strip
    const int q    = lane >> 2;     // 0..7
    const int tig  = lane & 3;      // 0..3
    const int rowBase = ROW0 + blockIdx.y * BM;
    const int colBase = blockIdx.x * BN;

    const uint32_t sA = (uint32_t)__cvta_generic_to_shared(As);
    const uint32_t sB = (uint32_t)__cvta_generic_to_shared(Bs);

    // ---- async staging, split into two K-halves (16 float4 columns each) ----
    #pragma unroll
    for (int h = 0; h < 2; h++) {
        #pragma unroll
        for (int t = 0; t < 2; t++) {           // A: 2048 float4 per half
            int idx = tid + t * 1024;
            int r = idx >> 4, c4 = (idx & 15) + h * 16;
            CP_ASYNC16(sA + (r * LDA + c4 * 4) * 4,
                       (const float4*)(g_fn + (size_t)(rowBase + r) * D) + c4);
        }
        #pragma unroll
        for (int t = 0; t < 4; t++) {           // B: 4096 float4 per half
            int idx = tid + t * 1024;
            int r = idx >> 4, c4 = (idx & 15) + h * 16;
            CP_ASYNC16(sB + (r * LDA + c4 * 4) * 4,
                       (const float4*)(g_fn + (size_t)(colBase + r) * D) + c4);
        }
        CP_COMMIT();
    }

    float acc[2][4][4];
    #pragma unroll
    for (int mt = 0; mt < 2; mt++)
        #pragma unroll
        for (int nt = 0; nt < 4; nt++)
            #pragma unroll
            for (int e = 0; e < 4; e++) acc[mt][nt][e] = 0.f;

    const uint32_t* Au = (const uint32_t*)As;
    const uint32_t* Bu = (const uint32_t*)Bs;
    const int aBase = (wm * 32 + q) * LDA + tig;
    const int bBase = (wn * 32 + q) * LDA + tig;

    CP_WAIT(1);            // K-half 0 resident
    __syncthreads();

    #pragma unroll
    for (int half = 0; half < 2; half++) {
        #pragma unroll
        for (int s = 0; s < 8; s++) {
            const int k0 = half * 64 + s * 8;
            uint32_t af[2][4];
            #pragma unroll
            for (int mt = 0; mt < 2; mt++) {
                int base = aBase + mt * 16 * LDA + k0;
                af[mt][0] = Au[base];
                af[mt][1] = Au[base + 8 * LDA];
                af[mt][2] = Au[base + 4];
                af[mt][3] = Au[base + 8 * LDA + 4];
            }
            uint32_t bf[4][2];
            #pragma unroll
            for (int nt = 0; nt < 4; nt++) {
                int base = bBase + nt * 8 * LDA + k0;
                bf[nt][0] = Bu[base];
                bf[nt][1] = Bu[base + 4];
            }
            #pragma unroll
            for (int mt = 0; mt < 2; mt++)
                #pragma unroll
                for (int nt = 0; nt < 4; nt++)
                    asm volatile(
                        "mma.sync.aligned.m16n8k8.row.col.f32.tf32.tf32.f32 "
                        "{%0,%1,%2,%3}, {%4,%5,%6,%7}, {%8,%9}, {%0,%1,%2,%3};"
                        : "+f"(acc[mt][nt][0]), "+f"(acc[mt][nt][1]),
                          "+f"(acc[mt][nt][2]), "+f"(acc[mt][nt][3])
                        : "r"(af[mt][0]), "r"(af[mt][1]), "r"(af[mt][2]), "r"(af[mt][3]),
                          "r"(bf[nt][0]), "r"(bf[nt][1]));
        }
        if (half == 0) {
            CP_WAIT(0);    // K-half 1 resident
            __syncthreads();
        }
    }
    __syncthreads();   // all smem reads done before pm overwrites As

    // ---- row max: thread -> quad shfl -> cross-warp via smem ----
    float* pm = As;    // [8(wn)][128]
    #pragma unroll
    for (int mt = 0; mt < 2; mt++) {
        float mlo = -2.f, mhi = -2.f;
        #pragma unroll
        for (int nt = 0; nt < 4; nt++) {
            mlo = fmaxf(mlo, fmaxf(acc[mt][nt][0], acc[mt][nt][1]));
            mhi = fmaxf(mhi, fmaxf(acc[mt][nt][2], acc[mt][nt][3]));
        }
        #pragma unroll
        for (int o = 1; o < 4; o <<= 1) {
            mlo = fmaxf(mlo, __shfl_xor_sync(0xffffffffu, mlo, o));
            mhi = fmaxf(mhi, __shfl_xor_sync(0xffffffffu, mhi, o));
        }
        if (tig == 0) {
            int r = wm * 32 + mt * 16 + q;
            pm[wn * 128 + r]     = mlo;
            pm[wn * 128 + r + 8] = mhi;
        }
    }
    __syncthreads();

    if (tid < BM) {
        float m = -2.f;
        #pragma unroll
        for (int j = 0; j < 8; j++) m = fmaxf(m, pm[j * 128 + tid]);
        g_part[blockIdx.x * IPC_C + blockIdx.y * BM + tid] = m;
    }
    __syncthreads();

    // ---- last-block-done fused finalize ----
    __shared__ int isLast;
    __shared__ float red[512];
    if (tid == 0) {
        __threadfence();
        isLast = (atomicAdd(&g_done, 1) == NBLK - 1);
    }
    __syncthreads();
    if (!isLast) return;
    if (tid == 0) __threadfence();
    __syncthreads();

    if (tid < 512) {
        float e = -2.f, h = -2.f;
        #pragma unroll
        for (int j = 0; j < ETIL; j++)     e = fmaxf(e, g_part[j * IPC_C + tid]);
        #pragma unroll
        for (int j = ETIL; j < NTIL; j++)  h = fmaxf(h, g_part[j * IPC_C + tid]);
        red[tid] = log1pf(expf((h - e) * 10.0f));   // 1/SIGMA1 = 10
    }
    __syncthreads();
    #pragma unroll
    for (int s2 = 256; s2; s2 >>= 1) {
        if (tid < s2) red[tid] += red[tid + s2];
        __syncthreads();
    }
    if (tid == 0) {
        out[0] = a_scl[0] * red[0] * (1.0f / 512.0f);
        g_done = 0;      // reset for the next graph replay
    }
}

extern "C" void kernel_launch(void* const* d_in, const int* in_sizes, int n_in,
                              void* d_out, int out_size) {
    const float* fvec = (const float*)d_in[0];   // [8192,128] f32
    // d_in[1] = Lvec (dead in the reference math)
    const float* a    = (const float*)d_in[2];   // scalar f32
    float* out = (float*)d_out;

    cudaFuncSetAttribute(gemm_kernel,
                         cudaFuncAttributeMaxDynamicSharedMemorySize,
                         SMEM_FLOATS * 4);

    prep_kernel<<<N_TOT / 8, 256>>>(fvec);
    gemm_kernel<<<dim3(NTIL, IPC_C / BM), 1024, SMEM_FLOATS * 4>>>(a, out);
}